// round 7
// baseline (speedup 1.0000x reference)
#include <cuda_runtime.h>
#include <math.h>

#define NB 16
#define NS 48
#define SEGLEN 20000
#define ND 256
#define NPIX 65536
#define NVW 512           // 16384 ver bits / 32
#define SIDX 3
#define EIDX 38
#define NSEG (EIDX - SIDX)   // 35
#define NITER 34
#define FLAT (NS*ND)

typedef unsigned long long ull;

// ---- scratch (device globals; no allocations) ----
__device__ unsigned g_histX[NB*NS*ND];
__device__ unsigned g_histY[NB*NS*ND];
__device__ float    g_m[2*NB*NS];          // centroids [axis][b][s]
__device__ int      g_al[2*NB*NS];         // aligned shifts [axis][b][s]
__device__ unsigned g_verseg[NB*NSEG*NVW]; // shifted 128x128 ver bitmaps
__device__ unsigned char g_commit[NB*NS];
__device__ int      g_container[NB*NPIX];
__device__ ull      g_acc[NB][2];          // per-batch s1,s2 partials

// ========== hist (R4-proven) + container/acc zeroing ==========
__global__ void k_hist(const float* __restrict__ ev){
    int s = blockIdx.x, b = blockIdx.y, t = threadIdx.x;   // 512 threads

    // zero container slice + acc (GMEM stores; off the smem/ATOMS path)
    {
        int base = (b*NS + s) * 1366;
        for(int i = t; i < 1366; i += 512){
            int idx = base + i;
            if(idx < NB*NPIX) g_container[idx] = 0;
        }
        if(s == 0 && b == 0 && t < NB*2) ((ull*)g_acc)[t] = 0;
    }

    __shared__ unsigned hx[ND][4], hy[ND][4];
    for(int i = t; i < ND*4; i += 512){
        ((unsigned*)hx)[i] = 0;
        ((unsigned*)hy)[i] = 0;
    }
    __syncthreads();

    const float4* p4 = reinterpret_cast<const float4*>(
        ev + 2*((size_t)b*(NS*SEGLEN) + (size_t)s*SEGLEN));
    int rep = t & 3;
    for(int i = t; i < SEGLEN/4; i += 512){
        float4 e0 = p4[i];
        float4 e1 = p4[i + SEGLEN/4];
        atomicAdd(&hx[(int)e0.x][rep], 1u);
        atomicAdd(&hy[(int)e0.y][rep], 1u);
        atomicAdd(&hx[(int)e0.z][rep], 1u);
        atomicAdd(&hy[(int)e0.w][rep], 1u);
        atomicAdd(&hx[(int)e1.x][rep], 1u);
        atomicAdd(&hy[(int)e1.y][rep], 1u);
        atomicAdd(&hx[(int)e1.z][rep], 1u);
        atomicAdd(&hy[(int)e1.w][rep], 1u);
    }
    __syncthreads();
    if(t < ND){
        g_histX[(b*NS+s)*ND + t] = hx[t][0] + hx[t][1] + hx[t][2] + hx[t][3];
        g_histY[(b*NS+s)*ND + t] = hy[t][0] + hy[t][1] + hy[t][2] + hy[t][3];
    }
}

// ============ stats: cv + separable blur/centroid -> g_m, g_al ============
__global__ void k_stats(){
    int b = blockIdx.x, ax = blockIdx.y, t = threadIdx.x;   // 512 threads
    __shared__ ull a1[512], a2[512];
    __shared__ double R[NS];
    __shared__ float cvs;
    __shared__ float mloc[NS];

    const unsigned* h = (ax ? g_histY : g_histX) + b*FLAT;

    ull s1 = 0, s2 = 0;
    for(int i = t; i < FLAT; i += 512){
        unsigned v = h[i];
        s1 += v; s2 += (ull)v*v;
    }
    a1[t] = s1; a2[t] = s2; __syncthreads();
    for(int o = 256; o; o >>= 1){
        if(t < o){ a1[t] += a1[t+o]; a2[t] += a2[t+o]; }
        __syncthreads();
    }
    if(t == 0){
        double n = (double)FLAT;
        double mean = (double)a1[0] / n;
        double var  = ((double)a2[0] - (double)a1[0]*(double)a1[0]/n) / (n - 1.0);
        cvs = (float)(mean + 3.0*sqrt(var));
    }
    __syncthreads();
    float cv = cvs;

    int w = t >> 5, lane = t & 31;
    for(int r = w; r < NS; r += 16){
        const unsigned* row = h + r*ND;
        double acc = 0.0;
        for(int d = lane; d < ND; d += 32){
            float v = fminf((float)row[d], cv);
            acc += (double)v * (double)d;
        }
        #pragma unroll
        for(int o = 16; o; o >>= 1)
            acc += __shfl_down_sync(0xffffffffu, acc, o);
        if(lane == 0){
            double e0   = (double)fminf((float)row[0],   cv);
            double e1   = (double)fminf((float)row[1],   cv);
            double e254 = (double)fminf((float)row[254], cv);
            double e255 = (double)fminf((float)row[255], cv);
            R[r] = 5.0*acc + 3.0*e0 + e1 - 256.0*e254 - 513.0*e255;
        }
    }
    __syncthreads();
    if(t < NS){
        double s = 0.0;
        int lo = t-2 < 0 ? 0 : t-2, hi = t+2 > NS-1 ? NS-1 : t+2;
        for(int i = lo; i <= hi; i++) s += R[i];
        mloc[t] = (float)((0.04 * s) / (double)SEGLEN);
        g_m[ax*NB*NS + b*NS + t] = mloc[t];
    }
    __syncthreads();
    if(t < NS){
        float st = mloc[SIDX];
        float al = rintf((mloc[t] - st) - (128.0f - st));   // exact ref op order
        g_al[ax*NB*NS + b*NS + t] = (int)al;
    }
}

// ========== per-segment ver bitmaps (parallel, MLP=4) ==========
__global__ void k_bitmap(const float* __restrict__ ev){
    int j = blockIdx.x, b = blockIdx.y, t = threadIdx.x;   // 512 threads
    int si = SIDX + j;
    __shared__ unsigned vbm[NVW];
    vbm[t] = 0;
    __syncthreads();
    int ax = g_al[b*NS + si], ay = g_al[NB*NS + b*NS + si];
    const float4* p = reinterpret_cast<const float4*>(
        ev + 2*((size_t)b*(NS*SEGLEN) + (size_t)si*SEGLEN));
    const int Q = SEGLEN/8;   // 2500 float4 per quarter
    for(int i = t; i < Q; i += 512){
        float4 e0 = p[i];
        float4 e1 = p[i + Q];
        float4 e2 = p[i + 2*Q];
        float4 e3 = p[i + 3*Q];
        #define VBIT(px, py) { \
            int xs = min(max((int)(px) - ax, 0), 255); \
            int ys = min(max((int)(py) - ay, 0), 255); \
            int iv = (xs >> 1) + ((ys >> 1) << 7); \
            atomicOr(&vbm[iv >> 5], 1u << (iv & 31)); }
        VBIT(e0.x, e0.y) VBIT(e0.z, e0.w)
        VBIT(e1.x, e1.y) VBIT(e1.z, e1.w)
        VBIT(e2.x, e2.y) VBIT(e2.z, e2.w)
        VBIT(e3.x, e3.y) VBIT(e3.z, e3.w)
        #undef VBIT
    }
    __syncthreads();
    g_verseg[(size_t)(b*NSEG + j)*NVW + t] = vbm[t];
}

// ========== scan: warp0 serial decisions, pipelined global loads ==========
__global__ void k_scan(){
    int b = blockIdx.x, t = threadIdx.x;   // 64 threads
    __shared__ float mm[2][NS];
    __shared__ unsigned char sout[NITER];

    if(t < NS) g_commit[b*NS + t] = 0;
    for(int i = t; i < 2*NS; i += 64)
        ((float*)mm)[i] = g_m[(i/NS)*NB*NS + b*NS + (i%NS)];
    __syncthreads();

    if(t < NITER){
        bool f = false;
        #pragma unroll
        for(int ax = 0; ax < 2; ax++){
            float w10[10], so[10], dd[10];
            for(int i = 0; i < 10; i++){ w10[i] = mm[ax][SIDX + 1 + t + i]; so[i] = w10[i]; }
            for(int i = 1; i < 10; i++){
                float k = so[i]; int j = i - 1;
                while(j >= 0 && so[j] > k){ so[j+1] = so[j]; j--; }
                so[j+1] = k;
            }
            float med = 0.5f*(so[4] + so[5]);
            for(int i = 0; i < 10; i++) dd[i] = fabsf(w10[i] - med);
            float d0 = dd[0];
            for(int i = 1; i < 10; i++){
                float k = dd[i]; int j = i - 1;
                while(j >= 0 && dd[j] > k){ dd[j+1] = dd[j]; j--; }
                dd[j+1] = k;
            }
            float mad = 0.5f*(dd[4] + dd[5]);
            bool fl = (mad == 0.0f) ? (d0 > 0.0f)
                                    : (__fdiv_rn(0.6745f*d0, mad) > 2.0f);
            f = f || fl;
        }
        sout[t] = f ? 1 : 0;
    }
    __syncthreads();

    if(t < 32){
        const unsigned* base = g_verseg + (size_t)b*NSEG*NVW;
        // load ver0 (segment SIDX), coalesced: lane reads words lane+32k
        unsigned va[16];
        unsigned c = 0;
        #pragma unroll
        for(int k = 0; k < 16; k++){
            va[k] = base[t + 32*k];
            c += __popc(va[k]);
        }
        unsigned cnt = __reduce_add_sync(0xffffffffu, c);
        if(t == 0) g_commit[b*NS + SIDX] = 1;

        // find first non-outlier segment and prefetch it
        int si = SIDX + 1;
        while(si < EIDX && sout[si - SIDX - 1]) si++;
        unsigned wv[16];
        if(si < EIDX){
            const unsigned* src = base + (si - SIDX)*NVW;
            #pragma unroll
            for(int k = 0; k < 16; k++) wv[k] = src[t + 32*k];
        }
        while(si < EIDX){
            // next non-outlier segment (for prefetch)
            int sn = si + 1;
            while(sn < EIDX && sout[sn - SIDX - 1]) sn++;
            unsigned nx[16];
            if(sn < EIDX){
                const unsigned* src = base + (sn - SIDX)*NVW;
                #pragma unroll
                for(int k = 0; k < 16; k++) nx[k] = src[t + 32*k];
            }
            unsigned nw = 0;
            #pragma unroll
            for(int k = 0; k < 16; k++) nw += __popc(wv[k] & ~va[k]);
            unsigned ni = __reduce_add_sync(0xffffffffu, nw);
            unsigned cn = cnt + ni;
            if(__fdiv_rn((float)ni, (float)cn) < 0.1f) break;   // stopped forever
            #pragma unroll
            for(int k = 0; k < 16; k++) va[k] |= wv[k];
            cnt = cn;
            if(t == 0) g_commit[b*NS + si] = 1;
            si = sn;
            #pragma unroll
            for(int k = 0; k < 16; k++) wv[k] = nx[k];
        }
    }
}

// ========== container scatter for committed segments ==========
__global__ void k_scatter(const float* __restrict__ ev){
    int si = SIDX + blockIdx.x, b = blockIdx.y, ck = blockIdx.z;   // z: 8 chunks
    if(!g_commit[b*NS + si]) return;
    int ax = g_al[b*NS + si], ay = g_al[NB*NS + b*NS + si];
    const float4* p = reinterpret_cast<const float4*>(
        ev + 2*((size_t)b*(NS*SEGLEN) + (size_t)si*SEGLEN));
    int* cont = g_container + b*NPIX;
    int lo = ck * (SEGLEN/16), hi = lo + (SEGLEN/16);   // 10000 f4 / 8 chunks
    for(int i = lo + threadIdx.x; i < hi; i += blockDim.x){
        float4 e = p[i];
        {
            int xs = min(max((int)e.x - ax, 0), 255);
            int ys = min(max((int)e.y - ay, 0), 255);
            atomicAdd(&cont[xs + (ys << 8)], 1);
        }
        {
            int xs = min(max((int)e.z - ax, 0), 255);
            int ys = min(max((int)e.w - ay, 0), 255);
            atomicAdd(&cont[xs + (ys << 8)], 1);
        }
    }
}

// ========== final stats ==========
__global__ void k_fstat(){
    int pb = blockIdx.x, b = blockIdx.y, t = threadIdx.x;
    const int* c = g_container + b*NPIX + pb*(NPIX/16);
    ull s1 = 0, s2 = 0;
    for(int i = t; i < NPIX/16; i += 512){
        unsigned v = (unsigned)c[i];
        s1 += v; s2 += (ull)v*v;
    }
    __shared__ ull a1[512], a2[512];
    a1[t] = s1; a2[t] = s2; __syncthreads();
    for(int o = 256; o; o >>= 1){
        if(t < o){ a1[t] += a1[t+o]; a2[t] += a2[t+o]; }
        __syncthreads();
    }
    if(t == 0){
        atomicAdd(&g_acc[b][0], a1[0]);
        atomicAdd(&g_acc[b][1], a2[0]);
    }
}

// ========== final normalize ==========
__global__ void k_fnorm(float* __restrict__ out){
    int idx = blockIdx.x*blockDim.x + threadIdx.x;
    int b = idx >> 16;
    __shared__ float scv;
    if(threadIdx.x == 0){
        double n = (double)NPIX;
        double s1 = (double)g_acc[b][0], s2 = (double)g_acc[b][1];
        double mean = s1 / n;
        double var  = (s2 - s1*s1/n) / (n - 1.0);
        scv = (float)(mean + 3.0*sqrt(var));
    }
    __syncthreads();
    float cv = scv;
    float v = fminf((float)g_container[idx], cv);
    out[idx] = __fdiv_rn(v, cv);
}

// ========== launch ==========
extern "C" void kernel_launch(void* const* d_in, const int* in_sizes, int n_in,
                              void* d_out, int out_size){
    const float* ev = (const float*)d_in[0];
    float* out = (float*)d_out;
    (void)in_sizes; (void)n_in; (void)out_size;

    { dim3 g(NS, NB);   k_hist  <<<g, 512>>>(ev); }
    { dim3 g(NB, 2);    k_stats <<<g, 512>>>(); }
    { dim3 g(NSEG, NB); k_bitmap<<<g, 512>>>(ev); }
    k_scan<<<NB, 64>>>();                              // profile slot #4
    { dim3 g(NSEG, NB, 8); k_scatter<<<g, 512>>>(ev); }
    { dim3 g(16, NB);   k_fstat <<<g, 512>>>(); }
    k_fnorm<<<NB*NPIX/1024, 1024>>>(out);
}

// round 8
// speedup vs baseline: 1.0304x; 1.0304x over previous
#include <cuda_runtime.h>
#include <math.h>

#define NB 16
#define NS 48
#define SEGLEN 20000
#define ND 256
#define NPIX 65536
#define NVW 512           // 16384 ver bits / 32
#define SIDX 3
#define EIDX 38
#define NSEG (EIDX - SIDX)   // 35
#define NITER 34
#define FLAT (NS*ND)

typedef unsigned long long ull;

// ---- scratch (device globals; no allocations) ----
__device__ unsigned g_histX[NB*NS*ND];
__device__ unsigned g_histY[NB*NS*ND];
__device__ float    g_m[2*NB*NS];          // centroids [axis][b][s]
__device__ int      g_al[2*NB*NS];         // aligned shifts [axis][b][s]
__device__ unsigned g_verseg[NB*NSEG*NVW]; // per-(b,seg) ver bitmaps
__device__ unsigned char g_commit[NB*NS];
__device__ int      g_container[NB*NPIX];
__device__ ull      g_acc[NB][2];          // per-batch s1,s2 partials

// ================= zero =================
__global__ void k_zero(){
    int i = blockIdx.x*blockDim.x + threadIdx.x;
    g_container[i] = 0;
    if(blockIdx.x == 0 && threadIdx.x < NB*2) ((ull*)g_acc)[threadIdx.x] = 0;
}

// ================= hist =================
__global__ void k_hist(const float* __restrict__ ev){
    int s = blockIdx.x, b = blockIdx.y, t = threadIdx.x;   // 512 threads

    __shared__ unsigned hx[ND][4], hy[ND][4];
    for(int i = t; i < ND*4; i += 512){
        ((unsigned*)hx)[i] = 0;
        ((unsigned*)hy)[i] = 0;
    }
    __syncthreads();

    const float4* p4 = reinterpret_cast<const float4*>(
        ev + 2*((size_t)b*(NS*SEGLEN) + (size_t)s*SEGLEN));
    int rep = t & 3;
    // two independent loads per iteration (disjoint halves) for MLP=2
    for(int i = t; i < SEGLEN/4; i += 512){
        float4 e0 = p4[i];
        float4 e1 = p4[i + SEGLEN/4];
        atomicAdd(&hx[(int)e0.x][rep], 1u);
        atomicAdd(&hy[(int)e0.y][rep], 1u);
        atomicAdd(&hx[(int)e0.z][rep], 1u);
        atomicAdd(&hy[(int)e0.w][rep], 1u);
        atomicAdd(&hx[(int)e1.x][rep], 1u);
        atomicAdd(&hy[(int)e1.y][rep], 1u);
        atomicAdd(&hx[(int)e1.z][rep], 1u);
        atomicAdd(&hy[(int)e1.w][rep], 1u);
    }
    __syncthreads();
    if(t < ND){
        g_histX[(b*NS+s)*ND + t] = hx[t][0] + hx[t][1] + hx[t][2] + hx[t][3];
        g_histY[(b*NS+s)*ND + t] = hy[t][0] + hy[t][1] + hy[t][2] + hy[t][3];
    }
}

// ============ stats: cv + separable blur/centroid -> g_m, g_al ============
__global__ void k_stats(){
    int b = blockIdx.x, ax = blockIdx.y, t = threadIdx.x;   // 512 threads
    __shared__ ull a1[512], a2[512];
    __shared__ double R[NS];
    __shared__ float cvs;
    __shared__ float mloc[NS];

    const unsigned* h = (ax ? g_histY : g_histX) + b*FLAT;

    ull s1 = 0, s2 = 0;
    for(int i = t; i < FLAT; i += 512){
        unsigned v = h[i];
        s1 += v; s2 += (ull)v*v;
    }
    a1[t] = s1; a2[t] = s2; __syncthreads();
    for(int o = 256; o; o >>= 1){
        if(t < o){ a1[t] += a1[t+o]; a2[t] += a2[t+o]; }
        __syncthreads();
    }
    if(t == 0){
        double n = (double)FLAT;
        double mean = (double)a1[0] / n;
        double var  = ((double)a2[0] - (double)a1[0]*(double)a1[0]/n) / (n - 1.0);
        cvs = (float)(mean + 3.0*sqrt(var));
    }
    __syncthreads();
    float cv = cvs;

    int w = t >> 5, lane = t & 31;
    for(int r = w; r < NS; r += 16){
        const unsigned* row = h + r*ND;
        double acc = 0.0;
        for(int d = lane; d < ND; d += 32){
            float v = fminf((float)row[d], cv);
            acc += (double)v * (double)d;
        }
        #pragma unroll
        for(int o = 16; o; o >>= 1)
            acc += __shfl_down_sync(0xffffffffu, acc, o);
        if(lane == 0){
            double e0   = (double)fminf((float)row[0],   cv);
            double e1   = (double)fminf((float)row[1],   cv);
            double e254 = (double)fminf((float)row[254], cv);
            double e255 = (double)fminf((float)row[255], cv);
            R[r] = 5.0*acc + 3.0*e0 + e1 - 256.0*e254 - 513.0*e255;
        }
    }
    __syncthreads();
    if(t < NS){
        double s = 0.0;
        int lo = t-2 < 0 ? 0 : t-2, hi = t+2 > NS-1 ? NS-1 : t+2;
        for(int i = lo; i <= hi; i++) s += R[i];
        mloc[t] = (float)((0.04 * s) / (double)SEGLEN);
        g_m[ax*NB*NS + b*NS + t] = mloc[t];
    }
    __syncthreads();
    if(t < NS){
        float st = mloc[SIDX];
        float al = rintf((mloc[t] - st) - (128.0f - st));   // exact ref op order
        g_al[ax*NB*NS + b*NS + t] = (int)al;
    }
}

// ================= per-segment ver bitmaps (parallel, MLP=2) =================
__global__ void k_bitmap(const float* __restrict__ ev){
    int j = blockIdx.x, b = blockIdx.y, t = threadIdx.x;   // 512 threads
    int si = SIDX + j;
    __shared__ unsigned vbm[NVW];
    vbm[t] = 0;
    __syncthreads();
    int ax = g_al[b*NS + si], ay = g_al[NB*NS + b*NS + si];
    const float4* p = reinterpret_cast<const float4*>(
        ev + 2*((size_t)b*(NS*SEGLEN) + (size_t)si*SEGLEN));
    for(int i = t; i < SEGLEN/4; i += 512){
        float4 e0 = p[i];
        float4 e1 = p[i + SEGLEN/4];
        {
            int xs = min(max((int)e0.x - ax, 0), 255);
            int ys = min(max((int)e0.y - ay, 0), 255);
            int iv = (xs >> 1) + ((ys >> 1) << 7);
            atomicOr(&vbm[iv >> 5], 1u << (iv & 31));
        }
        {
            int xs = min(max((int)e0.z - ax, 0), 255);
            int ys = min(max((int)e0.w - ay, 0), 255);
            int iv = (xs >> 1) + ((ys >> 1) << 7);
            atomicOr(&vbm[iv >> 5], 1u << (iv & 31));
        }
        {
            int xs = min(max((int)e1.x - ax, 0), 255);
            int ys = min(max((int)e1.y - ay, 0), 255);
            int iv = (xs >> 1) + ((ys >> 1) << 7);
            atomicOr(&vbm[iv >> 5], 1u << (iv & 31));
        }
        {
            int xs = min(max((int)e1.z - ax, 0), 255);
            int ys = min(max((int)e1.w - ay, 0), 255);
            int iv = (xs >> 1) + ((ys >> 1) << 7);
            atomicOr(&vbm[iv >> 5], 1u << (iv & 31));
        }
    }
    __syncthreads();
    g_verseg[(size_t)(b*NSEG + j)*NVW + t] = vbm[t];
}

// ---- branchless 10-element sort: optimal 29-comparator network ----
#define CSWAP(i,j) { float lo = fminf(v[i], v[j]); float hi = fmaxf(v[i], v[j]); v[i] = lo; v[j] = hi; }
__device__ __forceinline__ void sort10(float* v){
    CSWAP(0,5) CSWAP(1,6) CSWAP(2,7) CSWAP(3,8) CSWAP(4,9)
    CSWAP(0,3) CSWAP(5,8) CSWAP(1,4) CSWAP(6,9)
    CSWAP(0,2) CSWAP(3,6) CSWAP(7,9)
    CSWAP(0,1) CSWAP(2,4) CSWAP(5,7) CSWAP(8,9)
    CSWAP(1,2) CSWAP(3,5) CSWAP(4,6) CSWAP(7,8)
    CSWAP(1,3) CSWAP(2,5) CSWAP(4,7) CSWAP(6,8)
    CSWAP(2,3) CSWAP(4,5) CSWAP(6,7)
    CSWAP(3,4) CSWAP(5,6)
}
#undef CSWAP

// ================= scan over bitmaps (serial decisions) =================
__global__ void k_scan(){
    int b = blockIdx.x, t = threadIdx.x;   // 512 threads == NVW
    int w = t >> 5, lane = t & 31;
    __shared__ unsigned redbuf[16];
    __shared__ unsigned s_tot;
    __shared__ float mm[2][NS];
    __shared__ unsigned char sout[NITER];

    if(t < NS) g_commit[b*NS + t] = 0;
    if(t < 2*NS) ((float*)mm)[t] = g_m[(t/NS)*NB*NS + b*NS + (t%NS)];
    __syncthreads();

    // MAD outlier flags — branchless sorting networks (no divergence)
    if(t < NITER){
        bool f = false;
        #pragma unroll
        for(int ax = 0; ax < 2; ax++){
            float w10[10], v[10];
            #pragma unroll
            for(int i = 0; i < 10; i++){ w10[i] = mm[ax][SIDX + 1 + t + i]; v[i] = w10[i]; }
            sort10(v);
            float med = 0.5f*(v[4] + v[5]);
            float d0 = fabsf(w10[0] - med);
            #pragma unroll
            for(int i = 0; i < 10; i++) v[i] = fabsf(w10[i] - med);
            sort10(v);
            float mad = 0.5f*(v[4] + v[5]);
            bool fl = (mad == 0.0f) ? (d0 > 0.0f)
                                    : (__fdiv_rn(0.6745f*d0, mad) > 2.0f);
            f = f || fl;
        }
        sout[t] = f ? 1 : 0;
    }
    __syncthreads();

    // running ver = bitmap of segment SIDX
    unsigned va = g_verseg[(size_t)(b*NSEG + 0)*NVW + t];
    unsigned nb = __popc(va);
    #pragma unroll
    for(int o = 16; o; o >>= 1) nb += __shfl_down_sync(0xffffffffu, nb, o);
    if(lane == 0) redbuf[w] = nb;
    __syncthreads();
    if(t == 0){
        unsigned s = 0;
        for(int i = 0; i < 16; i++) s += redbuf[i];
        s_tot = s;
    }
    __syncthreads();
    unsigned cnt = s_tot;
    if(t == 0) g_commit[b*NS + SIDX] = 1;

    for(int si = SIDX + 1; si < EIDX; ++si){
        if(sout[si - SIDX - 1]) continue;     // outlier: skip, don't stop
        unsigned wv = g_verseg[(size_t)(b*NSEG + (si - SIDX))*NVW + t];
        unsigned nw = __popc(wv & ~va);
        #pragma unroll
        for(int o = 16; o; o >>= 1) nw += __shfl_down_sync(0xffffffffu, nw, o);
        if(lane == 0) redbuf[w] = nw;
        __syncthreads();
        if(t == 0){
            unsigned s = 0;
            for(int i = 0; i < 16; i++) s += redbuf[i];
            s_tot = s;
        }
        __syncthreads();
        unsigned ni = s_tot;
        unsigned cn = cnt + ni;
        if(__fdiv_rn((float)ni, (float)cn) < 0.1f) break;
        va |= wv;
        cnt = cn;
        if(t == 0) g_commit[b*NS + si] = 1;
        __syncthreads();
    }
}

// ================= container scatter for committed segments =================
__global__ void k_scatter(const float* __restrict__ ev){
    int si = SIDX + blockIdx.x, b = blockIdx.y, ck = blockIdx.z;   // z: 4 chunks
    if(!g_commit[b*NS + si]) return;
    int ax = g_al[b*NS + si], ay = g_al[NB*NS + b*NS + si];
    const float4* p = reinterpret_cast<const float4*>(
        ev + 2*((size_t)b*(NS*SEGLEN) + (size_t)si*SEGLEN));
    int* cont = g_container + b*NPIX;
    int lo = ck * (SEGLEN/8), hi = lo + (SEGLEN/8);
    for(int i = lo + threadIdx.x; i < hi; i += blockDim.x){
        float4 e = p[i];
        {
            int xs = min(max((int)e.x - ax, 0), 255);
            int ys = min(max((int)e.y - ay, 0), 255);
            atomicAdd(&cont[xs + (ys << 8)], 1);
        }
        {
            int xs = min(max((int)e.z - ax, 0), 255);
            int ys = min(max((int)e.w - ay, 0), 255);
            atomicAdd(&cont[xs + (ys << 8)], 1);
        }
    }
}

// ================= final stats: partial sums into g_acc =================
__global__ void k_fstat(){
    int pb = blockIdx.x, b = blockIdx.y, t = threadIdx.x;
    const int* c = g_container + b*NPIX + pb*(NPIX/16);
    ull s1 = 0, s2 = 0;
    for(int i = t; i < NPIX/16; i += 512){
        unsigned v = (unsigned)c[i];
        s1 += v; s2 += (ull)v*v;
    }
    __shared__ ull a1[512], a2[512];
    a1[t] = s1; a2[t] = s2; __syncthreads();
    for(int o = 256; o; o >>= 1){
        if(t < o){ a1[t] += a1[t+o]; a2[t] += a2[t+o]; }
        __syncthreads();
    }
    if(t == 0){
        atomicAdd(&g_acc[b][0], a1[0]);
        atomicAdd(&g_acc[b][1], a2[0]);
    }
}

// ================= final normalize =================
__global__ void k_fnorm(float* __restrict__ out){
    int idx = blockIdx.x*blockDim.x + threadIdx.x;
    int b = idx >> 16;
    __shared__ float scv;
    if(threadIdx.x == 0){
        double n = (double)NPIX;
        double s1 = (double)g_acc[b][0], s2 = (double)g_acc[b][1];
        double mean = s1 / n;
        double var  = (s2 - s1*s1/n) / (n - 1.0);
        scv = (float)(mean + 3.0*sqrt(var));
    }
    __syncthreads();
    float cv = scv;
    float v = fminf((float)g_container[idx], cv);
    out[idx] = __fdiv_rn(v, cv);
}

// ================= launch =================
extern "C" void kernel_launch(void* const* d_in, const int* in_sizes, int n_in,
                              void* d_out, int out_size){
    const float* ev = (const float*)d_in[0];
    float* out = (float*)d_out;
    (void)in_sizes; (void)n_in; (void)out_size;

    { dim3 g(NS, NB);   k_hist  <<<g, 512>>>(ev); }
    { dim3 g(NB, 2);    k_stats <<<g, 512>>>(); }
    { dim3 g(NSEG, NB); k_bitmap<<<g, 512>>>(ev); }
    k_scan<<<NB, NVW>>>();                             // profile slot #4
    k_zero<<<NB*NPIX/1024, 1024>>>();                  // before scatter is enough
    { dim3 g(NSEG, NB, 4); k_scatter<<<g, 512>>>(ev); }
    { dim3 g(16, NB);   k_fstat <<<g, 512>>>(); }
    k_fnorm<<<NB*NPIX/1024, 1024>>>(out);
}

// round 9
// speedup vs baseline: 1.4537x; 1.4108x over previous
#include <cuda_runtime.h>
#include <math.h>

#define NB 16
#define NS 48
#define SEGLEN 20000
#define ND 256
#define NPIX 65536
#define NVW 512           // 16384 ver bits / 32
#define SIDX 3
#define EIDX 38
#define NSEG (EIDX - SIDX)   // 35
#define K1 8                 // phase-1 segments
#define NITER 34
#define FLAT (NS*ND)

typedef unsigned long long ull;

// ---- scratch (device globals; no allocations) ----
__device__ unsigned g_histX[NB*NS*ND];
__device__ unsigned g_histY[NB*NS*ND];
__device__ float    g_m[2*NB*NS];          // centroids [axis][b][s]
__device__ int      g_al[2*NB*NS];         // aligned shifts [axis][b][s]
__device__ unsigned g_verseg[NB*NSEG*NVW]; // per-(b,seg) ver bitmaps
__device__ unsigned char g_commit[NB*NS];
__device__ unsigned char g_isout[NB*NITER];
__device__ int      g_done[NB];
__device__ unsigned g_cnt[NB];
__device__ unsigned g_vasave[NB][NVW];
__device__ int      g_container[NB*NPIX];
__device__ ull      g_acc[NB][2];          // per-batch s1,s2 partials

// ================= hist (R4-proven) =================
__global__ void k_hist(const float* __restrict__ ev){
    int s = blockIdx.x, b = blockIdx.y, t = threadIdx.x;   // 512 threads

    __shared__ unsigned hx[ND][4], hy[ND][4];
    for(int i = t; i < ND*4; i += 512){
        ((unsigned*)hx)[i] = 0;
        ((unsigned*)hy)[i] = 0;
    }
    __syncthreads();

    const float4* p4 = reinterpret_cast<const float4*>(
        ev + 2*((size_t)b*(NS*SEGLEN) + (size_t)s*SEGLEN));
    int rep = t & 3;
    for(int i = t; i < SEGLEN/4; i += 512){
        float4 e0 = p4[i];
        float4 e1 = p4[i + SEGLEN/4];
        atomicAdd(&hx[(int)e0.x][rep], 1u);
        atomicAdd(&hy[(int)e0.y][rep], 1u);
        atomicAdd(&hx[(int)e0.z][rep], 1u);
        atomicAdd(&hy[(int)e0.w][rep], 1u);
        atomicAdd(&hx[(int)e1.x][rep], 1u);
        atomicAdd(&hy[(int)e1.y][rep], 1u);
        atomicAdd(&hx[(int)e1.z][rep], 1u);
        atomicAdd(&hy[(int)e1.w][rep], 1u);
    }
    __syncthreads();
    if(t < ND){
        g_histX[(b*NS+s)*ND + t] = hx[t][0] + hx[t][1] + hx[t][2] + hx[t][3];
        g_histY[(b*NS+s)*ND + t] = hy[t][0] + hy[t][1] + hy[t][2] + hy[t][3];
    }
}

// ============ stats: cv + separable blur/centroid -> g_m, g_al ============
__global__ void k_stats(){
    int b = blockIdx.x, ax = blockIdx.y, t = threadIdx.x;   // 512 threads
    __shared__ ull a1[512], a2[512];
    __shared__ double R[NS];
    __shared__ float cvs;
    __shared__ float mloc[NS];

    if(b == 0 && ax == 0 && t < NB*2) ((ull*)g_acc)[t] = 0;

    const unsigned* h = (ax ? g_histY : g_histX) + b*FLAT;

    ull s1 = 0, s2 = 0;
    for(int i = t; i < FLAT; i += 512){
        unsigned v = h[i];
        s1 += v; s2 += (ull)v*v;
    }
    a1[t] = s1; a2[t] = s2; __syncthreads();
    for(int o = 256; o; o >>= 1){
        if(t < o){ a1[t] += a1[t+o]; a2[t] += a2[t+o]; }
        __syncthreads();
    }
    if(t == 0){
        double n = (double)FLAT;
        double mean = (double)a1[0] / n;
        double var  = ((double)a2[0] - (double)a1[0]*(double)a1[0]/n) / (n - 1.0);
        cvs = (float)(mean + 3.0*sqrt(var));
    }
    __syncthreads();
    float cv = cvs;

    int w = t >> 5, lane = t & 31;
    for(int r = w; r < NS; r += 16){
        const unsigned* row = h + r*ND;
        double acc = 0.0;
        for(int d = lane; d < ND; d += 32){
            float v = fminf((float)row[d], cv);
            acc += (double)v * (double)d;
        }
        #pragma unroll
        for(int o = 16; o; o >>= 1)
            acc += __shfl_down_sync(0xffffffffu, acc, o);
        if(lane == 0){
            double e0   = (double)fminf((float)row[0],   cv);
            double e1   = (double)fminf((float)row[1],   cv);
            double e254 = (double)fminf((float)row[254], cv);
            double e255 = (double)fminf((float)row[255], cv);
            R[r] = 5.0*acc + 3.0*e0 + e1 - 256.0*e254 - 513.0*e255;
        }
    }
    __syncthreads();
    if(t < NS){
        double s = 0.0;
        int lo = t-2 < 0 ? 0 : t-2, hi = t+2 > NS-1 ? NS-1 : t+2;
        for(int i = lo; i <= hi; i++) s += R[i];
        mloc[t] = (float)((0.04 * s) / (double)SEGLEN);
        g_m[ax*NB*NS + b*NS + t] = mloc[t];
    }
    __syncthreads();
    if(t < NS){
        float st = mloc[SIDX];
        float al = rintf((mloc[t] - st) - (128.0f - st));   // exact ref op order
        g_al[ax*NB*NS + b*NS + t] = (int)al;
    }
}

// ---- bitmap builder body (shared by both phases) ----
__device__ __forceinline__ void bitmap_body(const float* __restrict__ ev, int b, int j, int t){
    int si = SIDX + j;
    __shared__ unsigned vbm[NVW];
    vbm[t] = 0;
    __syncthreads();
    int ax = g_al[b*NS + si], ay = g_al[NB*NS + b*NS + si];
    const float4* p = reinterpret_cast<const float4*>(
        ev + 2*((size_t)b*(NS*SEGLEN) + (size_t)si*SEGLEN));
    for(int i = t; i < SEGLEN/4; i += 512){
        float4 e0 = p[i];
        float4 e1 = p[i + SEGLEN/4];
        #define VBIT(px, py) { \
            int xs = min(max((int)(px) - ax, 0), 255); \
            int ys = min(max((int)(py) - ay, 0), 255); \
            int iv = (xs >> 1) + ((ys >> 1) << 7); \
            atomicOr(&vbm[iv >> 5], 1u << (iv & 31)); }
        VBIT(e0.x, e0.y) VBIT(e0.z, e0.w)
        VBIT(e1.x, e1.y) VBIT(e1.z, e1.w)
        #undef VBIT
    }
    __syncthreads();
    g_verseg[(size_t)(b*NSEG + j)*NVW + t] = vbm[t];
}

// ========== phase-1 bitmaps (j < K1) + container zeroing ==========
__global__ void k_bitmap1(const float* __restrict__ ev){
    int j = blockIdx.x, b = blockIdx.y, t = threadIdx.x;   // 512 threads
    // zero container slice (128 blocks x 8192 ints = full 16*65536)
    {
        int base = (b*K1 + j) * 8192;
        int4 z = make_int4(0,0,0,0);
        int4* dst = (int4*)(g_container + base);
        for(int i = t; i < 2048; i += 512) dst[i] = z;
    }
    bitmap_body(ev, b, j, t);
}

// ========== phase-2 bitmaps (j >= K1), skipped when batch done ==========
__global__ void k_bitmap2(const float* __restrict__ ev){
    int j = K1 + blockIdx.x, b = blockIdx.y, t = threadIdx.x;
    if(g_done[b]) return;
    bitmap_body(ev, b, j, t);
}

// ---- branchless 10-element sort: optimal 29-comparator network ----
#define CSWAP(i,j) { float lo = fminf(v[i], v[j]); float hi = fmaxf(v[i], v[j]); v[i] = lo; v[j] = hi; }
__device__ __forceinline__ void sort10(float* v){
    CSWAP(0,5) CSWAP(1,6) CSWAP(2,7) CSWAP(3,8) CSWAP(4,9)
    CSWAP(0,3) CSWAP(5,8) CSWAP(1,4) CSWAP(6,9)
    CSWAP(0,2) CSWAP(3,6) CSWAP(7,9)
    CSWAP(0,1) CSWAP(2,4) CSWAP(5,7) CSWAP(8,9)
    CSWAP(1,2) CSWAP(3,5) CSWAP(4,6) CSWAP(7,8)
    CSWAP(1,3) CSWAP(2,5) CSWAP(4,7) CSWAP(6,8)
    CSWAP(2,3) CSWAP(4,5) CSWAP(6,7)
    CSWAP(3,4) CSWAP(5,6)
}
#undef CSWAP

// ========== phase-1 scan: segments SIDX+1 .. SIDX+K1-1 ==========
__global__ void k_scan1(){
    int b = blockIdx.x, t = threadIdx.x;   // 512 threads == NVW
    int w = t >> 5, lane = t & 31;
    __shared__ unsigned redbuf[16];
    __shared__ unsigned s_tot;
    __shared__ float mm[2][NS];
    __shared__ unsigned char sout[NITER];
    __shared__ int s_done;

    if(t < NS) g_commit[b*NS + t] = 0;
    if(t < 2*NS) ((float*)mm)[t] = g_m[(t/NS)*NB*NS + b*NS + (t%NS)];
    __syncthreads();

    // MAD outlier flags — branchless sorting networks
    if(t < NITER){
        bool f = false;
        #pragma unroll
        for(int ax = 0; ax < 2; ax++){
            float w10[10], v[10];
            #pragma unroll
            for(int i = 0; i < 10; i++){ w10[i] = mm[ax][SIDX + 1 + t + i]; v[i] = w10[i]; }
            sort10(v);
            float med = 0.5f*(v[4] + v[5]);
            float d0 = fabsf(w10[0] - med);
            #pragma unroll
            for(int i = 0; i < 10; i++) v[i] = fabsf(w10[i] - med);
            sort10(v);
            float mad = 0.5f*(v[4] + v[5]);
            bool fl = (mad == 0.0f) ? (d0 > 0.0f)
                                    : (__fdiv_rn(0.6745f*d0, mad) > 2.0f);
            f = f || fl;
        }
        sout[t] = f ? 1 : 0;
        g_isout[b*NITER + t] = f ? 1 : 0;
    }
    if(t == 0) s_done = 0;
    __syncthreads();

    unsigned va = g_verseg[(size_t)(b*NSEG + 0)*NVW + t];
    unsigned nb = __popc(va);
    #pragma unroll
    for(int o = 16; o; o >>= 1) nb += __shfl_down_sync(0xffffffffu, nb, o);
    if(lane == 0) redbuf[w] = nb;
    __syncthreads();
    if(t == 0){
        unsigned s = 0;
        for(int i = 0; i < 16; i++) s += redbuf[i];
        s_tot = s;
    }
    __syncthreads();
    unsigned cnt = s_tot;
    if(t == 0) g_commit[b*NS + SIDX] = 1;

    for(int si = SIDX + 1; si < SIDX + K1; ++si){
        if(sout[si - SIDX - 1]) continue;     // outlier: skip, don't stop
        unsigned wv = g_verseg[(size_t)(b*NSEG + (si - SIDX))*NVW + t];
        unsigned nw = __popc(wv & ~va);
        #pragma unroll
        for(int o = 16; o; o >>= 1) nw += __shfl_down_sync(0xffffffffu, nw, o);
        if(lane == 0) redbuf[w] = nw;
        __syncthreads();
        if(t == 0){
            unsigned s = 0;
            for(int i = 0; i < 16; i++) s += redbuf[i];
            s_tot = s;
        }
        __syncthreads();
        unsigned ni = s_tot;
        unsigned cn = cnt + ni;
        if(__fdiv_rn((float)ni, (float)cn) < 0.1f){    // stopped forever
            if(t == 0) s_done = 1;
            break;
        }
        va |= wv;
        cnt = cn;
        if(t == 0) g_commit[b*NS + si] = 1;
        __syncthreads();
    }
    __syncthreads();
    // spill state for phase 2
    g_vasave[b][t] = va;
    if(t == 0){
        g_done[b] = s_done;
        g_cnt[b]  = cnt;
    }
}

// ========== phase-2 scan: segments SIDX+K1 .. EIDX-1 ==========
__global__ void k_scan2(){
    int b = blockIdx.x, t = threadIdx.x;   // 512 threads
    if(g_done[b]) return;                  // uniform per block
    int w = t >> 5, lane = t & 31;
    __shared__ unsigned redbuf[16];
    __shared__ unsigned s_tot;
    __shared__ unsigned char sout[NITER];

    if(t < NITER) sout[t] = g_isout[b*NITER + t];
    __syncthreads();

    unsigned va = g_vasave[b][t];
    unsigned cnt = g_cnt[b];

    for(int si = SIDX + K1; si < EIDX; ++si){
        if(sout[si - SIDX - 1]) continue;
        unsigned wv = g_verseg[(size_t)(b*NSEG + (si - SIDX))*NVW + t];
        unsigned nw = __popc(wv & ~va);
        #pragma unroll
        for(int o = 16; o; o >>= 1) nw += __shfl_down_sync(0xffffffffu, nw, o);
        if(lane == 0) redbuf[w] = nw;
        __syncthreads();
        if(t == 0){
            unsigned s = 0;
            for(int i = 0; i < 16; i++) s += redbuf[i];
            s_tot = s;
        }
        __syncthreads();
        unsigned ni = s_tot;
        unsigned cn = cnt + ni;
        if(__fdiv_rn((float)ni, (float)cn) < 0.1f) break;
        va |= wv;
        cnt = cn;
        if(t == 0) g_commit[b*NS + si] = 1;
        __syncthreads();
    }
}

// ================= container scatter for committed segments =================
__global__ void k_scatter(const float* __restrict__ ev){
    int si = SIDX + blockIdx.x, b = blockIdx.y, ck = blockIdx.z;   // z: 4 chunks
    if(!g_commit[b*NS + si]) return;
    int ax = g_al[b*NS + si], ay = g_al[NB*NS + b*NS + si];
    const float4* p = reinterpret_cast<const float4*>(
        ev + 2*((size_t)b*(NS*SEGLEN) + (size_t)si*SEGLEN));
    int* cont = g_container + b*NPIX;
    int lo = ck * (SEGLEN/8), hi = lo + (SEGLEN/8);
    for(int i = lo + threadIdx.x; i < hi; i += blockDim.x){
        float4 e = p[i];
        {
            int xs = min(max((int)e.x - ax, 0), 255);
            int ys = min(max((int)e.y - ay, 0), 255);
            atomicAdd(&cont[xs + (ys << 8)], 1);
        }
        {
            int xs = min(max((int)e.z - ax, 0), 255);
            int ys = min(max((int)e.w - ay, 0), 255);
            atomicAdd(&cont[xs + (ys << 8)], 1);
        }
    }
}

// ================= final stats: partial sums into g_acc =================
__global__ void k_fstat(){
    int pb = blockIdx.x, b = blockIdx.y, t = threadIdx.x;
    const int* c = g_container + b*NPIX + pb*(NPIX/16);
    ull s1 = 0, s2 = 0;
    for(int i = t; i < NPIX/16; i += 512){
        unsigned v = (unsigned)c[i];
        s1 += v; s2 += (ull)v*v;
    }
    __shared__ ull a1[512], a2[512];
    a1[t] = s1; a2[t] = s2; __syncthreads();
    for(int o = 256; o; o >>= 1){
        if(t < o){ a1[t] += a1[t+o]; a2[t] += a2[t+o]; }
        __syncthreads();
    }
    if(t == 0){
        atomicAdd(&g_acc[b][0], a1[0]);
        atomicAdd(&g_acc[b][1], a2[0]);
    }
}

// ================= final normalize =================
__global__ void k_fnorm(float* __restrict__ out){
    int idx = blockIdx.x*blockDim.x + threadIdx.x;
    int b = idx >> 16;
    __shared__ float scv;
    if(threadIdx.x == 0){
        double n = (double)NPIX;
        double s1 = (double)g_acc[b][0], s2 = (double)g_acc[b][1];
        double mean = s1 / n;
        double var  = (s2 - s1*s1/n) / (n - 1.0);
        scv = (float)(mean + 3.0*sqrt(var));
    }
    __syncthreads();
    float cv = scv;
    float v = fminf((float)g_container[idx], cv);
    out[idx] = __fdiv_rn(v, cv);
}

// ================= launch =================
extern "C" void kernel_launch(void* const* d_in, const int* in_sizes, int n_in,
                              void* d_out, int out_size){
    const float* ev = (const float*)d_in[0];
    float* out = (float*)d_out;
    (void)in_sizes; (void)n_in; (void)out_size;

    { dim3 g(NS, NB);        k_hist   <<<g, 512>>>(ev); }
    { dim3 g(NB, 2);         k_stats  <<<g, 512>>>(); }
    { dim3 g(K1, NB);        k_bitmap1<<<g, 512>>>(ev); }
    k_scan1<<<NB, NVW>>>();                               // profile slot #4
    { dim3 g(NSEG - K1, NB); k_bitmap2<<<g, 512>>>(ev); }
    k_scan2<<<NB, NVW>>>();
    { dim3 g(NSEG, NB, 4);   k_scatter<<<g, 512>>>(ev); }
    { dim3 g(16, NB);        k_fstat  <<<g, 512>>>(); }
    k_fnorm<<<NB*NPIX/1024, 1024>>>(out);
}

// round 10
// speedup vs baseline: 1.4823x; 1.0196x over previous
#include <cuda_runtime.h>
#include <math.h>

#define NB 16
#define NS 48
#define SEGLEN 20000
#define ND 256
#define NPIX 65536
#define NVW 512           // 16384 ver bits / 32
#define SIDX 3
#define EIDX 38
#define NSEG (EIDX - SIDX)   // 35
#define K1 8                 // phase-1 segments
#define NITER 34
#define FLAT (NS*ND)

typedef unsigned long long ull;

// ---- scratch (device globals; no allocations) ----
__device__ unsigned g_histX[NB*NS*ND];
__device__ unsigned g_histY[NB*NS*ND];
__device__ float    g_m[2*NB*NS];          // centroids [axis][b][s]
__device__ int      g_al[2*NB*NS];         // aligned shifts [axis][b][s]
__device__ unsigned g_verseg[NB*NSEG*NVW]; // per-(b,seg) ver bitmaps
__device__ unsigned char g_commit[NB*NS];
__device__ unsigned char g_isout[NB*NITER];
__device__ int      g_done[NB];
__device__ unsigned g_cnt[NB];
__device__ unsigned g_vasave[NB][NVW];
__device__ int      g_container[NB*NPIX];
__device__ ull      g_acc[NB][2];          // per-batch s1,s2 partials

// ================= hist (R4-proven) =================
__global__ void k_hist(const float* __restrict__ ev){
    int s = blockIdx.x, b = blockIdx.y, t = threadIdx.x;   // 512 threads

    __shared__ unsigned hx[ND][4], hy[ND][4];
    for(int i = t; i < ND*4; i += 512){
        ((unsigned*)hx)[i] = 0;
        ((unsigned*)hy)[i] = 0;
    }
    __syncthreads();

    const float4* p4 = reinterpret_cast<const float4*>(
        ev + 2*((size_t)b*(NS*SEGLEN) + (size_t)s*SEGLEN));
    int rep = t & 3;
    for(int i = t; i < SEGLEN/4; i += 512){
        float4 e0 = p4[i];
        float4 e1 = p4[i + SEGLEN/4];
        atomicAdd(&hx[(int)e0.x][rep], 1u);
        atomicAdd(&hy[(int)e0.y][rep], 1u);
        atomicAdd(&hx[(int)e0.z][rep], 1u);
        atomicAdd(&hy[(int)e0.w][rep], 1u);
        atomicAdd(&hx[(int)e1.x][rep], 1u);
        atomicAdd(&hy[(int)e1.y][rep], 1u);
        atomicAdd(&hx[(int)e1.z][rep], 1u);
        atomicAdd(&hy[(int)e1.w][rep], 1u);
    }
    __syncthreads();
    if(t < ND){
        g_histX[(b*NS+s)*ND + t] = hx[t][0] + hx[t][1] + hx[t][2] + hx[t][3];
        g_histY[(b*NS+s)*ND + t] = hy[t][0] + hy[t][1] + hy[t][2] + hy[t][3];
    }
}

// ============ stats: cv + separable blur/centroid -> g_m, g_al ============
__global__ void k_stats(){
    int b = blockIdx.x, ax = blockIdx.y, t = threadIdx.x;   // 512 threads
    __shared__ ull a1[512], a2[512];
    __shared__ double R[NS];
    __shared__ float cvs;
    __shared__ float mloc[NS];

    if(b == 0 && ax == 0 && t < NB*2) ((ull*)g_acc)[t] = 0;

    const unsigned* h = (ax ? g_histY : g_histX) + b*FLAT;

    ull s1 = 0, s2 = 0;
    for(int i = t; i < FLAT; i += 512){
        unsigned v = h[i];
        s1 += v; s2 += (ull)v*v;
    }
    a1[t] = s1; a2[t] = s2; __syncthreads();
    for(int o = 256; o; o >>= 1){
        if(t < o){ a1[t] += a1[t+o]; a2[t] += a2[t+o]; }
        __syncthreads();
    }
    if(t == 0){
        double n = (double)FLAT;
        double mean = (double)a1[0] / n;
        double var  = ((double)a2[0] - (double)a1[0]*(double)a1[0]/n) / (n - 1.0);
        cvs = (float)(mean + 3.0*sqrt(var));
    }
    __syncthreads();
    float cv = cvs;

    int w = t >> 5, lane = t & 31;
    for(int r = w; r < NS; r += 16){
        const unsigned* row = h + r*ND;
        double acc = 0.0;
        for(int d = lane; d < ND; d += 32){
            float v = fminf((float)row[d], cv);
            acc += (double)v * (double)d;
        }
        #pragma unroll
        for(int o = 16; o; o >>= 1)
            acc += __shfl_down_sync(0xffffffffu, acc, o);
        if(lane == 0){
            double e0   = (double)fminf((float)row[0],   cv);
            double e1   = (double)fminf((float)row[1],   cv);
            double e254 = (double)fminf((float)row[254], cv);
            double e255 = (double)fminf((float)row[255], cv);
            R[r] = 5.0*acc + 3.0*e0 + e1 - 256.0*e254 - 513.0*e255;
        }
    }
    __syncthreads();
    if(t < NS){
        double s = 0.0;
        int lo = t-2 < 0 ? 0 : t-2, hi = t+2 > NS-1 ? NS-1 : t+2;
        for(int i = lo; i <= hi; i++) s += R[i];
        mloc[t] = (float)((0.04 * s) / (double)SEGLEN);
        g_m[ax*NB*NS + b*NS + t] = mloc[t];
    }
    __syncthreads();
    if(t < NS){
        float st = mloc[SIDX];
        float al = rintf((mloc[t] - st) - (128.0f - st));   // exact ref op order
        g_al[ax*NB*NS + b*NS + t] = (int)al;
    }
}

// ---- bitmap builder body (shared by both phases) ----
__device__ __forceinline__ void bitmap_body(const float* __restrict__ ev, int b, int j, int t){
    int si = SIDX + j;
    __shared__ unsigned vbm[NVW];
    vbm[t] = 0;
    __syncthreads();
    int ax = g_al[b*NS + si], ay = g_al[NB*NS + b*NS + si];
    const float4* p = reinterpret_cast<const float4*>(
        ev + 2*((size_t)b*(NS*SEGLEN) + (size_t)si*SEGLEN));
    for(int i = t; i < SEGLEN/4; i += 512){
        float4 e0 = p[i];
        float4 e1 = p[i + SEGLEN/4];
        #define VBIT(px, py) { \
            int xs = min(max((int)(px) - ax, 0), 255); \
            int ys = min(max((int)(py) - ay, 0), 255); \
            int iv = (xs >> 1) + ((ys >> 1) << 7); \
            atomicOr(&vbm[iv >> 5], 1u << (iv & 31)); }
        VBIT(e0.x, e0.y) VBIT(e0.z, e0.w)
        VBIT(e1.x, e1.y) VBIT(e1.z, e1.w)
        #undef VBIT
    }
    __syncthreads();
    g_verseg[(size_t)(b*NSEG + j)*NVW + t] = vbm[t];
}

// ========== phase-1 bitmaps (j < K1) + container zeroing ==========
__global__ void k_bitmap1(const float* __restrict__ ev){
    int j = blockIdx.x, b = blockIdx.y, t = threadIdx.x;   // 512 threads
    {
        int base = (b*K1 + j) * 8192;
        int4 z = make_int4(0,0,0,0);
        int4* dst = (int4*)(g_container + base);
        for(int i = t; i < 2048; i += 512) dst[i] = z;
    }
    bitmap_body(ev, b, j, t);
}

// ========== phase-2 bitmaps (j >= K1), skipped when batch done ==========
__global__ void k_bitmap2(const float* __restrict__ ev){
    int j = K1 + blockIdx.x, b = blockIdx.y, t = threadIdx.x;
    if(g_done[b]) return;
    bitmap_body(ev, b, j, t);
}

// ---- branchless 10-element sort: optimal 29-comparator network ----
#define CSWAP(i,j) { float lo = fminf(v[i], v[j]); float hi = fmaxf(v[i], v[j]); v[i] = lo; v[j] = hi; }
__device__ __forceinline__ void sort10(float* v){
    CSWAP(0,5) CSWAP(1,6) CSWAP(2,7) CSWAP(3,8) CSWAP(4,9)
    CSWAP(0,3) CSWAP(5,8) CSWAP(1,4) CSWAP(6,9)
    CSWAP(0,2) CSWAP(3,6) CSWAP(7,9)
    CSWAP(0,1) CSWAP(2,4) CSWAP(5,7) CSWAP(8,9)
    CSWAP(1,2) CSWAP(3,5) CSWAP(4,6) CSWAP(7,8)
    CSWAP(1,3) CSWAP(2,5) CSWAP(4,7) CSWAP(6,8)
    CSWAP(2,3) CSWAP(4,5) CSWAP(6,7)
    CSWAP(3,4) CSWAP(5,6)
}
#undef CSWAP

// ========== phase-1 scan: smem-staged bitmaps, serial decisions ==========
__global__ void k_scan1(){
    int b = blockIdx.x, t = threadIdx.x;   // 512 threads == NVW
    int w = t >> 5, lane = t & 31;
    __shared__ unsigned sver[K1][NVW];     // 16KB: all phase-1 bitmaps
    __shared__ unsigned redbuf[16];
    __shared__ unsigned s_tot;
    __shared__ float mm[2][NS];
    __shared__ unsigned char sout[NITER];
    __shared__ int s_done;

    if(t < NS) g_commit[b*NS + t] = 0;
    if(t < 2*NS) ((float*)mm)[t] = g_m[(t/NS)*NB*NS + b*NS + (t%NS)];
    // parallel preload: 8 overlapping coalesced bursts
    {
        const unsigned* src = g_verseg + (size_t)b*NSEG*NVW;
        #pragma unroll
        for(int j = 0; j < K1; j++) sver[j][t] = src[j*NVW + t];
    }
    if(t == 0) s_done = 0;
    __syncthreads();

    // MAD outlier flags — branchless sorting networks
    if(t < NITER){
        bool f = false;
        #pragma unroll
        for(int ax = 0; ax < 2; ax++){
            float w10[10], v[10];
            #pragma unroll
            for(int i = 0; i < 10; i++){ w10[i] = mm[ax][SIDX + 1 + t + i]; v[i] = w10[i]; }
            sort10(v);
            float med = 0.5f*(v[4] + v[5]);
            float d0 = fabsf(w10[0] - med);
            #pragma unroll
            for(int i = 0; i < 10; i++) v[i] = fabsf(w10[i] - med);
            sort10(v);
            float mad = 0.5f*(v[4] + v[5]);
            bool fl = (mad == 0.0f) ? (d0 > 0.0f)
                                    : (__fdiv_rn(0.6745f*d0, mad) > 2.0f);
            f = f || fl;
        }
        sout[t] = f ? 1 : 0;
        g_isout[b*NITER + t] = f ? 1 : 0;
    }
    __syncthreads();

    unsigned va = sver[0][t];
    unsigned nb = __popc(va);
    #pragma unroll
    for(int o = 16; o; o >>= 1) nb += __shfl_down_sync(0xffffffffu, nb, o);
    if(lane == 0) redbuf[w] = nb;
    __syncthreads();
    if(t == 0){
        unsigned s = 0;
        for(int i = 0; i < 16; i++) s += redbuf[i];
        s_tot = s;
    }
    __syncthreads();
    unsigned cnt = s_tot;
    if(t == 0) g_commit[b*NS + SIDX] = 1;

    for(int si = SIDX + 1; si < SIDX + K1; ++si){
        if(sout[si - SIDX - 1]) continue;     // outlier: skip, don't stop
        unsigned wv = sver[si - SIDX][t];
        unsigned nw = __popc(wv & ~va);
        #pragma unroll
        for(int o = 16; o; o >>= 1) nw += __shfl_down_sync(0xffffffffu, nw, o);
        if(lane == 0) redbuf[w] = nw;
        __syncthreads();
        if(t == 0){
            unsigned s = 0;
            for(int i = 0; i < 16; i++) s += redbuf[i];
            s_tot = s;
        }
        __syncthreads();
        unsigned ni = s_tot;
        unsigned cn = cnt + ni;
        if(__fdiv_rn((float)ni, (float)cn) < 0.1f){    // stopped forever
            if(t == 0) s_done = 1;
            break;
        }
        va |= wv;
        cnt = cn;
        if(t == 0) g_commit[b*NS + si] = 1;
        __syncthreads();
    }
    __syncthreads();
    // spill state for phase 2
    g_vasave[b][t] = va;
    if(t == 0){
        g_done[b] = s_done;
        g_cnt[b]  = cnt;
    }
}

// ========== phase-2 scan: segments SIDX+K1 .. EIDX-1 ==========
__global__ void k_scan2(){
    int b = blockIdx.x, t = threadIdx.x;   // 512 threads
    if(g_done[b]) return;                  // uniform per block
    int w = t >> 5, lane = t & 31;
    __shared__ unsigned redbuf[16];
    __shared__ unsigned s_tot;
    __shared__ unsigned char sout[NITER];

    if(t < NITER) sout[t] = g_isout[b*NITER + t];
    __syncthreads();

    unsigned va = g_vasave[b][t];
    unsigned cnt = g_cnt[b];

    for(int si = SIDX + K1; si < EIDX; ++si){
        if(sout[si - SIDX - 1]) continue;
        unsigned wv = g_verseg[(size_t)(b*NSEG + (si - SIDX))*NVW + t];
        unsigned nw = __popc(wv & ~va);
        #pragma unroll
        for(int o = 16; o; o >>= 1) nw += __shfl_down_sync(0xffffffffu, nw, o);
        if(lane == 0) redbuf[w] = nw;
        __syncthreads();
        if(t == 0){
            unsigned s = 0;
            for(int i = 0; i < 16; i++) s += redbuf[i];
            s_tot = s;
        }
        __syncthreads();
        unsigned ni = s_tot;
        unsigned cn = cnt + ni;
        if(__fdiv_rn((float)ni, (float)cn) < 0.1f) break;
        va |= wv;
        cnt = cn;
        if(t == 0) g_commit[b*NS + si] = 1;
        __syncthreads();
    }
}

// ================= container scatter for committed segments =================
__global__ void k_scatter(const float* __restrict__ ev){
    int si = SIDX + blockIdx.x, b = blockIdx.y, ck = blockIdx.z;   // z: 8 chunks
    if(!g_commit[b*NS + si]) return;
    int ax = g_al[b*NS + si], ay = g_al[NB*NS + b*NS + si];
    const float4* p = reinterpret_cast<const float4*>(
        ev + 2*((size_t)b*(NS*SEGLEN) + (size_t)si*SEGLEN));
    int* cont = g_container + b*NPIX;
    int lo = ck * (SEGLEN/16), hi = lo + (SEGLEN/16);   // 10000 f4 / 8
    for(int i = lo + threadIdx.x; i < hi; i += blockDim.x){
        float4 e = p[i];
        {
            int xs = min(max((int)e.x - ax, 0), 255);
            int ys = min(max((int)e.y - ay, 0), 255);
            atomicAdd(&cont[xs + (ys << 8)], 1);
        }
        {
            int xs = min(max((int)e.z - ax, 0), 255);
            int ys = min(max((int)e.w - ay, 0), 255);
            atomicAdd(&cont[xs + (ys << 8)], 1);
        }
    }
}

// ================= final stats: partial sums into g_acc =================
__global__ void k_fstat(){
    int pb = blockIdx.x, b = blockIdx.y, t = threadIdx.x;
    const int* c = g_container + b*NPIX + pb*(NPIX/16);
    ull s1 = 0, s2 = 0;
    for(int i = t; i < NPIX/16; i += 512){
        unsigned v = (unsigned)c[i];
        s1 += v; s2 += (ull)v*v;
    }
    __shared__ ull a1[512], a2[512];
    a1[t] = s1; a2[t] = s2; __syncthreads();
    for(int o = 256; o; o >>= 1){
        if(t < o){ a1[t] += a1[t+o]; a2[t] += a2[t+o]; }
        __syncthreads();
    }
    if(t == 0){
        atomicAdd(&g_acc[b][0], a1[0]);
        atomicAdd(&g_acc[b][1], a2[0]);
    }
}

// ================= final normalize =================
__global__ void k_fnorm(float* __restrict__ out){
    int idx = blockIdx.x*blockDim.x + threadIdx.x;
    int b = idx >> 16;
    __shared__ float scv;
    if(threadIdx.x == 0){
        double n = (double)NPIX;
        double s1 = (double)g_acc[b][0], s2 = (double)g_acc[b][1];
        double mean = s1 / n;
        double var  = (s2 - s1*s1/n) / (n - 1.0);
        scv = (float)(mean + 3.0*sqrt(var));
    }
    __syncthreads();
    float cv = scv;
    float v = fminf((float)g_container[idx], cv);
    out[idx] = __fdiv_rn(v, cv);
}

// ================= launch =================
extern "C" void kernel_launch(void* const* d_in, const int* in_sizes, int n_in,
                              void* d_out, int out_size){
    const float* ev = (const float*)d_in[0];
    float* out = (float*)d_out;
    (void)in_sizes; (void)n_in; (void)out_size;

    { dim3 g(NS, NB);        k_hist   <<<g, 512>>>(ev); }
    { dim3 g(NB, 2);         k_stats  <<<g, 512>>>(); }
    { dim3 g(K1, NB);        k_bitmap1<<<g, 512>>>(ev); }
    k_scan1<<<NB, NVW>>>();                               // profile slot #4
    { dim3 g(NSEG - K1, NB); k_bitmap2<<<g, 512>>>(ev); }
    k_scan2<<<NB, NVW>>>();
    { dim3 g(NSEG, NB, 8);   k_scatter<<<g, 512>>>(ev); }
    { dim3 g(16, NB);        k_fstat  <<<g, 512>>>(); }
    k_fnorm<<<NB*NPIX/1024, 1024>>>(out);
}